// round 9
// baseline (speedup 1.0000x reference)
#include <cuda_runtime.h>
#include <math.h>

// Problem constants (shapes fixed by the dataset)
#define MAX_N 50000
#define MAX_E 800000
#define FIN   256
#define HC    256     // H1*C1
#define H1N   4
#define C1N   64
#define F2    16

// ---------------- scratch (static device globals; no allocation) -------------
__device__ float g_h1 [MAX_N * HC];   // x@W1
__device__ float g_h1o[MAX_N * HC];   // layer1 output (bias+relu)
__device__ float g_h2 [MAX_N * F2];   // h1o@W2
__device__ float g_as1[MAX_N * H1N];
__device__ float g_ad1[MAX_N * H1N];
__device__ float g_as2[MAX_N];
__device__ float g_ad2[MAX_N];
__device__ int   g_deg [MAX_N];
__device__ int   g_cur [MAX_N];
__device__ int   g_offs[MAX_N + 1];
__device__ int   g_csr [MAX_E];       // src node ids grouped by dst

#define NEGBIG (-3.0e38f)

// ---------------- CSR build --------------------------------------------------
__global__ void init_kernel(int N) {
    int i = blockIdx.x * blockDim.x + threadIdx.x;
    if (i < N) { g_deg[i] = 0; g_cur[i] = 0; }
}

// edge_index is INT32 (JAX x64 disabled: randint(dtype=int64) silently yields int32)
__global__ void deg_kernel(const int* __restrict__ ei, int E) {
    int e = blockIdx.x * blockDim.x + threadIdx.x;
    if (e < E) {
        int d = ei[E + e];
        if (d >= 0 && d < MAX_N) atomicAdd(&g_deg[d], 1);
    }
}

// single-block exclusive scan of g_deg -> g_offs (N up to 50000)
__global__ void scan_kernel(int N) {
    __shared__ int wsum[32];
    __shared__ int carry_sh;
    int t = threadIdx.x;
    if (t == 0) carry_sh = 0;
    __syncthreads();
    for (int base = 0; base < N; base += 1024) {
        int i = base + t;
        int v = (i < N) ? g_deg[i] : 0;
        int x = v;
        #pragma unroll
        for (int o = 1; o < 32; o <<= 1) {
            int y = __shfl_up_sync(0xffffffffu, x, o);
            if ((t & 31) >= o) x += y;
        }
        if ((t & 31) == 31) wsum[t >> 5] = x;
        __syncthreads();
        if (t < 32) {
            int w = wsum[t];
            #pragma unroll
            for (int o = 1; o < 32; o <<= 1) {
                int y = __shfl_up_sync(0xffffffffu, w, o);
                if (t >= o) w += y;
            }
            wsum[t] = w;
        }
        __syncthreads();
        int incl = x + ((t >= 32) ? wsum[(t >> 5) - 1] : 0);
        int carry = carry_sh;
        if (i < N) g_offs[i] = carry + incl - v;   // exclusive
        __syncthreads();
        if (t == 1023) carry_sh = carry + incl;    // tile total
        __syncthreads();
    }
    if (t == 0) g_offs[N] = carry_sh;
}

__global__ void fill_kernel(const int* __restrict__ ei, int E) {
    int e = blockIdx.x * blockDim.x + threadIdx.x;
    if (e < E) {
        int d = ei[E + e];
        if (d >= 0 && d < MAX_N) {
            int pos = g_offs[d] + atomicAdd(&g_cur[d], 1);
            g_csr[pos] = ei[e];
        }
    }
}

// ---------------- GEMM1: h1 = x @ W1  (M x 256 @ 256 x 256) ------------------
#define GP 132
__global__ __launch_bounds__(256) void gemm1_kernel(
    const float* __restrict__ A, const float* __restrict__ B, int M)
{
    __shared__ float As[16][GP];
    __shared__ float Bs[16][GP];
    int t  = threadIdx.x;
    int n0 = blockIdx.x * 128;
    int m0 = blockIdx.y * 128;
    int tx = t & 15, ty = t >> 4;
    float acc[8][8];
    #pragma unroll
    for (int i = 0; i < 8; i++)
        #pragma unroll
        for (int j = 0; j < 8; j++) acc[i][j] = 0.f;

    for (int k0 = 0; k0 < 256; k0 += 16) {
        #pragma unroll
        for (int u = 0; u < 2; u++) {
            int idx = t + u * 256;
            int r = idx >> 2, c4 = idx & 3;
            float4 v = make_float4(0.f, 0.f, 0.f, 0.f);
            int gr = m0 + r;
            if (gr < M)
                v = *reinterpret_cast<const float4*>(A + (size_t)gr * 256 + k0 + c4 * 4);
            As[c4 * 4 + 0][r] = v.x; As[c4 * 4 + 1][r] = v.y;
            As[c4 * 4 + 2][r] = v.z; As[c4 * 4 + 3][r] = v.w;
        }
        #pragma unroll
        for (int u = 0; u < 2; u++) {
            int idx = t + u * 256;
            int r = idx >> 5, c4 = idx & 31;
            float4 v = *reinterpret_cast<const float4*>(B + (size_t)(k0 + r) * 256 + n0 + c4 * 4);
            Bs[r][c4 * 4 + 0] = v.x; Bs[r][c4 * 4 + 1] = v.y;
            Bs[r][c4 * 4 + 2] = v.z; Bs[r][c4 * 4 + 3] = v.w;
        }
        __syncthreads();
        #pragma unroll
        for (int k = 0; k < 16; k++) {
            float ra[8], rb[8];
            #pragma unroll
            for (int i = 0; i < 8; i++) ra[i] = As[k][ty * 8 + i];
            #pragma unroll
            for (int i = 0; i < 8; i++) rb[i] = Bs[k][tx * 8 + i];
            #pragma unroll
            for (int i = 0; i < 8; i++)
                #pragma unroll
                for (int j = 0; j < 8; j++) acc[i][j] += ra[i] * rb[j];
        }
        __syncthreads();
    }
    #pragma unroll
    for (int i = 0; i < 8; i++) {
        int gr = m0 + ty * 8 + i;
        if (gr < M) {
            #pragma unroll
            for (int j = 0; j < 8; j++)
                g_h1[(size_t)gr * 256 + n0 + tx * 8 + j] = acc[i][j];
        }
    }
}

// ---------------- attention scores layer1 ------------------------------------
__global__ __launch_bounds__(256) void attn1_kernel(
    const float* __restrict__ att_s, const float* __restrict__ att_d)
{
    int n = blockIdx.x, t = threadIdx.x;
    float v  = g_h1[(size_t)n * HC + t];
    float ps = v * att_s[t], pd = v * att_d[t];
    #pragma unroll
    for (int o = 16; o > 0; o >>= 1) {
        ps += __shfl_down_sync(0xffffffffu, ps, o);
        pd += __shfl_down_sync(0xffffffffu, pd, o);
    }
    __shared__ float S[8], D[8];
    if ((t & 31) == 0) { S[t >> 5] = ps; D[t >> 5] = pd; }
    __syncthreads();
    if (t < H1N) {
        g_as1[n * H1N + t] = S[2 * t] + S[2 * t + 1];
        g_ad1[n * H1N + t] = D[2 * t] + D[2 * t + 1];
    }
}

// ---------------- fused per-dst softmax + aggregation, layer1 ----------------
__global__ __launch_bounds__(256) void node1_kernel(const float* __restrict__ b1)
{
    int n = blockIdx.x;
    int t = threadIdx.x;
    int off = g_offs[n];
    int deg = g_offs[n + 1] - off;
    int E = deg + 1;                 // +1 self loop

    __shared__ float sh_ad[H1N], sh_m[H1N], sh_inv[H1N];
    __shared__ float rm[8][H1N], rs[8][H1N];
    __shared__ int   ssrc[32];
    __shared__ float sw[H1N * 32];

    if (t < H1N) sh_ad[t] = g_ad1[n * H1N + t];
    __syncthreads();
    float adv[4] = { sh_ad[0], sh_ad[1], sh_ad[2], sh_ad[3] };

    // phase 1: online softmax (m, s) per head
    float m[4] = { NEGBIG, NEGBIG, NEGBIG, NEGBIG };
    float s[4] = { 0.f, 0.f, 0.f, 0.f };
    for (int i = t; i < E; i += 256) {
        int src = (i < deg) ? g_csr[off + i] : n;
        #pragma unroll
        for (int h = 0; h < 4; h++) {
            float lr = g_as1[src * 4 + h] + adv[h];
            lr = lr > 0.f ? lr : 0.2f * lr;
            if (lr > m[h]) { s[h] = s[h] * __expf(m[h] - lr) + 1.f; m[h] = lr; }
            else           { s[h] += __expf(lr - m[h]); }
        }
    }
    #pragma unroll
    for (int o = 16; o > 0; o >>= 1) {
        #pragma unroll
        for (int h = 0; h < 4; h++) {
            float m2 = __shfl_down_sync(0xffffffffu, m[h], o);
            float s2 = __shfl_down_sync(0xffffffffu, s[h], o);
            if (m2 > m[h]) { s[h] = s[h] * __expf(m[h] - m2) + s2; m[h] = m2; }
            else           { s[h] += s2 * __expf(m2 - m[h]); }
        }
    }
    if ((t & 31) == 0) {
        #pragma unroll
        for (int h = 0; h < 4; h++) { rm[t >> 5][h] = m[h]; rs[t >> 5][h] = s[h]; }
    }
    __syncthreads();
    if (t < H1N) {
        float M = NEGBIG, S = 0.f;
        #pragma unroll
        for (int w = 0; w < 8; w++) {
            float m2 = rm[w][t], s2 = rs[w][t];
            if (m2 > M) { S = S * __expf(M - m2) + s2; M = m2; }
            else        { S += s2 * __expf(m2 - M); }
        }
        sh_m[t] = M; sh_inv[t] = 1.f / (S + 1e-16f);
    }
    __syncthreads();

    // phase 2: alpha-weighted gather; thread t owns channel t
    int h = t >> 6;
    float acc = 0.f;
    for (int base = 0; base < E; base += 32) {
        int cnt = min(32, E - base);
        __syncthreads();
        if (t < cnt) {
            int i = base + t;
            int src = (i < deg) ? g_csr[off + i] : n;
            ssrc[t] = src;
            #pragma unroll
            for (int hh = 0; hh < 4; hh++) {
                float lr = g_as1[src * 4 + hh] + sh_ad[hh];
                lr = lr > 0.f ? lr : 0.2f * lr;
                sw[hh * 32 + t] = __expf(lr - sh_m[hh]) * sh_inv[hh];
            }
        }
        __syncthreads();
        const float* swh = &sw[h * 32];
        for (int j = 0; j < cnt; j++)
            acc += g_h1[(size_t)ssrc[j] * HC + t] * swh[j];
    }
    float v = acc + b1[t];
    g_h1o[(size_t)n * HC + t] = v > 0.f ? v : 0.f;
}

// ---------------- GEMM2 (+ attention-score epilogue) -------------------------
__global__ __launch_bounds__(256) void gemm2_kernel(
    const float* __restrict__ W2, const float* __restrict__ att_s,
    const float* __restrict__ att_d, int N)
{
    __shared__ float Ws[HC * F2];   // 16 KB
    int t = threadIdx.x;
    for (int i = t; i < HC * F2; i += 256) Ws[i] = W2[i];
    __syncthreads();
    int r = t >> 4, j = t & 15;
    int n = blockIdx.x * 16 + r;
    int nn = n < N ? n : N - 1;
    const float* xr = g_h1o + (size_t)nn * HC;
    float acc = 0.f;
    #pragma unroll 8
    for (int k = 0; k < HC; k++) acc += xr[k] * Ws[k * F2 + j];
    float ps = acc * att_s[j], pd = acc * att_d[j];
    #pragma unroll
    for (int o = 8; o > 0; o >>= 1) {
        ps += __shfl_xor_sync(0xffffffffu, ps, o);
        pd += __shfl_xor_sync(0xffffffffu, pd, o);
    }
    if (n < N) {
        g_h2[n * F2 + j] = acc;
        if (j == 0) { g_as2[n] = ps; g_ad2[n] = pd; }
    }
}

// ---------------- fused per-dst softmax + aggregation + log_softmax, layer2 --
__global__ __launch_bounds__(128) void node2_kernel(
    const float* __restrict__ b2, float* __restrict__ out)
{
    int n = blockIdx.x, t = threadIdx.x;
    int off = g_offs[n], deg = g_offs[n + 1] - off, E = deg + 1;

    __shared__ float sh_ad, sh_m, sh_inv;
    __shared__ float rm[4], rs[4];
    __shared__ int   ssrc[32];
    __shared__ float sw[32];
    __shared__ float sacc[128];
    __shared__ float sv[16];

    if (t == 0) sh_ad = g_ad2[n];
    __syncthreads();
    float ad = sh_ad;

    float m = NEGBIG, s = 0.f;
    for (int i = t; i < E; i += 128) {
        int src = (i < deg) ? g_csr[off + i] : n;
        float lr = g_as2[src] + ad;
        lr = lr > 0.f ? lr : 0.2f * lr;
        if (lr > m) { s = s * __expf(m - lr) + 1.f; m = lr; }
        else        { s += __expf(lr - m); }
    }
    #pragma unroll
    for (int o = 16; o > 0; o >>= 1) {
        float m2 = __shfl_down_sync(0xffffffffu, m, o);
        float s2 = __shfl_down_sync(0xffffffffu, s, o);
        if (m2 > m) { s = s * __expf(m - m2) + s2; m = m2; }
        else        { s += s2 * __expf(m2 - m); }
    }
    if ((t & 31) == 0) { rm[t >> 5] = m; rs[t >> 5] = s; }
    __syncthreads();
    if (t == 0) {
        float M = NEGBIG, S = 0.f;
        #pragma unroll
        for (int w = 0; w < 4; w++) {
            float m2 = rm[w], s2 = rs[w];
            if (m2 > M) { S = S * __expf(M - m2) + s2; M = m2; }
            else        { S += s2 * __expf(m2 - M); }
        }
        sh_m = M; sh_inv = 1.f / (S + 1e-16f);
    }
    __syncthreads();
    float fm = sh_m, fi = sh_inv;

    int g = t >> 4, c = t & 15;
    float acc = 0.f;
    for (int base = 0; base < E; base += 32) {
        int cnt = min(32, E - base);
        __syncthreads();
        if (t < cnt) {
            int i = base + t;
            int src = (i < deg) ? g_csr[off + i] : n;
            ssrc[t] = src;
            float lr = g_as2[src] + ad;
            lr = lr > 0.f ? lr : 0.2f * lr;
            sw[t] = __expf(lr - fm) * fi;
        }
        __syncthreads();
        for (int j = g; j < cnt; j += 8)
            acc += g_h2[ssrc[j] * F2 + c] * sw[j];
    }
    sacc[t] = acc;
    __syncthreads();
    if (t < 16) {
        float v = 0.f;
        #pragma unroll
        for (int w = 0; w < 8; w++) v += sacc[w * 16 + t];
        sv[t] = v + b2[t];
    }
    __syncthreads();
    if (t < 16) {
        float mx = NEGBIG;
        #pragma unroll
        for (int j = 0; j < 16; j++) mx = fmaxf(mx, sv[j]);
        float se = 0.f;
        #pragma unroll
        for (int j = 0; j < 16; j++) se += expf(sv[j] - mx);
        out[n * F2 + t] = sv[t] - mx - logf(se);
    }
}

// ---------------- launch -----------------------------------------------------
extern "C" void kernel_launch(void* const* d_in, const int* in_sizes, int n_in,
                              void* d_out, int out_size)
{
    const float* x   = (const float*)d_in[0];
    const int*   ei  = (const int*)d_in[1];   // int32! (JAX x64 disabled)
    const float* W1  = (const float*)d_in[2];
    const float* as1 = (const float*)d_in[3];
    const float* ad1 = (const float*)d_in[4];
    const float* b1  = (const float*)d_in[5];
    const float* W2  = (const float*)d_in[6];
    const float* as2 = (const float*)d_in[7];
    const float* ad2 = (const float*)d_in[8];
    const float* b2  = (const float*)d_in[9];
    float* out = (float*)d_out;

    int N = in_sizes[0] / FIN;   // 50000
    int E = in_sizes[1] / 2;     // 800000

    init_kernel<<<(N + 255) / 256, 256>>>(N);
    deg_kernel<<<(E + 255) / 256, 256>>>(ei, E);
    scan_kernel<<<1, 1024>>>(N);
    fill_kernel<<<(E + 255) / 256, 256>>>(ei, E);

    gemm1_kernel<<<dim3(2, (N + 127) / 128), 256>>>(x, W1, N);
    attn1_kernel<<<N, 256>>>(as1, ad1);
    node1_kernel<<<N, 256>>>(b1);

    gemm2_kernel<<<(N + 15) / 16, 256>>>(W2, as2, ad2, N);
    node2_kernel<<<N, 128>>>(b2, out);
}